// round 1
// baseline (speedup 1.0000x reference)
#include <cuda_runtime.h>
#include <cstdint>

#define NN 100000
#define EE 1600000
#define HF 128          // HEADS * OUT_F
#define NB_SCAN 98      // ceil(NN/1024)

// ---------------- scratch (static __device__, no allocations) ----------------
__device__ float g_h[NN * HF];          // 51.2 MB : h = x @ W
__device__ float g_asrc[NN * 4];        // per-node per-head attention (src side)
__device__ float g_adst[NN * 4];        // per-node per-head attention (dst side)
__device__ int   g_deg[NN];             // in-degree incl self loop
__device__ int   g_cursor[NN];          // scatter cursors
__device__ int   g_rowstart[NN + 1];    // CSR row offsets by destination
__device__ int   g_srcs[EE + NN];       // source node per sorted edge
__device__ int   g_bsums[NB_SCAN];      // scan partials
__device__ int   g_is64;                // 1 if edge_index is int64, else int32

// ---------------- dtype detection (int64 vs int32 edge_index) ----------------
__global__ void detect_dtype_kernel(const int* ei32) {
    __shared__ int nz;
    if (threadIdx.x == 0) nz = 0;
    __syncthreads();
    // If data is little-endian int64 with values < 2^31, every odd int32 word is 0.
    int v = ei32[threadIdx.x * 2 + 1];
    if (v != 0) atomicAdd(&nz, 1);
    __syncthreads();
    if (threadIdx.x == 0) g_is64 = (nz == 0) ? 1 : 0;
}

// ---------------- fused GEMM + attention-logit epilogue ----------------
// h[row, c] = sum_k x[row,k] * W[k,c];   a_src/a_dst[row,head] = <h[row,head,:], att[head,:]>
// One warp computes 4 rows; lane owns columns [lane*4, lane*4+4).
__global__ __launch_bounds__(256) void gemm_att_kernel(
    const float* __restrict__ x, const float* __restrict__ W,
    const float* __restrict__ att_src, const float* __restrict__ att_dst) {
    __shared__ float xs[32 * HF];  // 32 rows of x per block (16 KB)
    const int warp = threadIdx.x >> 5;
    const int lane = threadIdx.x & 31;
    const int row0 = blockIdx.x * 32 + warp * 4;

    // stage this warp's 4 rows of x into smem
#pragma unroll
    for (int r = 0; r < 4; r++) {
        int row = row0 + r;
        float4 v = make_float4(0.f, 0.f, 0.f, 0.f);
        if (row < NN) v = *(const float4*)(x + (size_t)row * HF + lane * 4);
        *(float4*)(xs + (warp * 4 + r) * HF + lane * 4) = v;
    }
    __syncwarp();

    float4 acc[4];
#pragma unroll
    for (int r = 0; r < 4; r++) acc[r] = make_float4(0.f, 0.f, 0.f, 0.f);

#pragma unroll 4
    for (int k = 0; k < HF; k++) {
        float4 w4 = *(const float4*)(W + k * HF + lane * 4);
#pragma unroll
        for (int r = 0; r < 4; r++) {
            float xk = xs[(warp * 4 + r) * HF + k];  // smem broadcast
            acc[r].x += xk * w4.x;
            acc[r].y += xk * w4.y;
            acc[r].z += xk * w4.z;
            acc[r].w += xk * w4.w;
        }
    }

    const int head = lane >> 3;           // 8 lanes per head (32 features / 4 per lane)
    const int fo   = (lane & 7) * 4;      // feature offset within head
    float4 s4 = *(const float4*)(att_src + head * 32 + fo);
    float4 d4 = *(const float4*)(att_dst + head * 32 + fo);

#pragma unroll
    for (int r = 0; r < 4; r++) {
        int row = row0 + r;
        if (row >= NN) continue;
        *(float4*)(g_h + (size_t)row * HF + lane * 4) = acc[r];
        float ps = acc[r].x * s4.x + acc[r].y * s4.y + acc[r].z * s4.z + acc[r].w * s4.w;
        float pd = acc[r].x * d4.x + acc[r].y * d4.y + acc[r].z * d4.z + acc[r].w * d4.w;
        // reduce over the 8 lanes of this head (lanes are contiguous groups of 8)
#pragma unroll
        for (int o = 1; o < 8; o <<= 1) {
            ps += __shfl_xor_sync(0xFFFFFFFFu, ps, o);
            pd += __shfl_xor_sync(0xFFFFFFFFu, pd, o);
        }
        if ((lane & 7) == 0) {
            g_asrc[row * 4 + head] = ps;
            g_adst[row * 4 + head] = pd;
        }
    }
}

// ---------------- CSR build ----------------
__global__ void init_deg_kernel() {
    int i = blockIdx.x * blockDim.x + threadIdx.x;
    if (i < NN) { g_deg[i] = 1; g_cursor[i] = 0; }  // deg=1 accounts for self loop
}

__global__ void count_deg_kernel(const void* eiv) {
    int t = blockIdx.x * blockDim.x + threadIdx.x;
    if (t >= EE) return;
    int dst;
    if (g_is64) dst = (int)((const long long*)eiv)[EE + t];
    else        dst = ((const int*)eiv)[EE + t];
    atomicAdd(&g_deg[dst], 1);
}

__global__ void scan_block_kernel() {
    __shared__ int sm[1024];
    int i = blockIdx.x * 1024 + threadIdx.x;
    int v = (i < NN) ? g_deg[i] : 0;
    sm[threadIdx.x] = v;
    __syncthreads();
    for (int o = 1; o < 1024; o <<= 1) {
        int t = (threadIdx.x >= (unsigned)o) ? sm[threadIdx.x - o] : 0;
        __syncthreads();
        sm[threadIdx.x] += t;
        __syncthreads();
    }
    if (i < NN) g_rowstart[i] = sm[threadIdx.x] - v;  // exclusive within block
    if (threadIdx.x == 1023) g_bsums[blockIdx.x] = sm[1023];
}

__global__ void scan_sums_kernel() {
    if (threadIdx.x == 0) {
        int acc = 0;
        for (int b = 0; b < NB_SCAN; b++) { int v = g_bsums[b]; g_bsums[b] = acc; acc += v; }
    }
}

__global__ void scan_add_kernel() {
    int i = blockIdx.x * 1024 + threadIdx.x;
    if (i < NN) g_rowstart[i] += g_bsums[blockIdx.x];
    if (blockIdx.x == 0 && threadIdx.x == 0) g_rowstart[NN] = EE + NN;  // total is known
}

__global__ void scatter_kernel(const void* eiv) {
    int t = blockIdx.x * blockDim.x + threadIdx.x;
    if (t >= EE + NN) return;
    int s, d;
    if (t < EE) {
        if (g_is64) {
            s = (int)((const long long*)eiv)[t];
            d = (int)((const long long*)eiv)[EE + t];
        } else {
            s = ((const int*)eiv)[t];
            d = ((const int*)eiv)[EE + t];
        }
    } else {
        s = d = t - EE;  // self loop
    }
    int p = atomicAdd(&g_cursor[d], 1);
    g_srcs[g_rowstart[d] + p] = s;
}

// ---------------- per-destination softmax + weighted aggregation ----------------
// One warp per destination node; lane owns 4 output features.
// softmax is shift-invariant: skip segment_max (|e| small here), exact in fp32.
__global__ __launch_bounds__(256) void aggregate_kernel(
    const float* __restrict__ bias, float* __restrict__ out) {
    const int warp = threadIdx.x >> 5;
    const int lane = threadIdx.x & 31;
    const int i = blockIdx.x * 8 + warp;
    if (i >= NN) return;

    const int head = lane >> 3;
    const float adst = g_adst[i * 4 + head];
    const int start = g_rowstart[i];
    const int end   = g_rowstart[i + 1];

    float4 acc = make_float4(0.f, 0.f, 0.f, 0.f);
    float ssum = 0.f;

    int src_next = g_srcs[start];  // segment always non-empty (self loop)
    for (int j = start; j < end; j++) {
        int src = src_next;
        if (j + 1 < end) src_next = g_srcs[j + 1];
        float e = g_asrc[src * 4 + head] + adst;
        e = (e > 0.f) ? e : 0.2f * e;          // leaky relu
        float w = __expf(e);
        float4 hv = *(const float4*)(g_h + (size_t)src * HF + lane * 4);
        ssum += w;
        acc.x += w * hv.x;
        acc.y += w * hv.y;
        acc.z += w * hv.z;
        acc.w += w * hv.w;
    }

    float inv = 1.f / ssum;
    float4 b = *(const float4*)(bias + lane * 4);
    float4 o;
    o.x = acc.x * inv + b.x;
    o.y = acc.y * inv + b.y;
    o.z = acc.z * inv + b.z;
    o.w = acc.w * inv + b.w;
    *(float4*)(out + (size_t)i * HF + lane * 4) = o;
}

// ---------------- launch ----------------
extern "C" void kernel_launch(void* const* d_in, const int* in_sizes, int n_in,
                              void* d_out, int out_size) {
    const float* x    = (const float*)d_in[0];
    const void*  ei   = d_in[1];
    const float* W    = (const float*)d_in[2];
    const float* asv  = (const float*)d_in[3];
    const float* adv  = (const float*)d_in[4];
    const float* bias = (const float*)d_in[5];
    float* out = (float*)d_out;

    detect_dtype_kernel<<<1, 256>>>((const int*)ei);
    gemm_att_kernel<<<(NN + 31) / 32, 256>>>(x, W, asv, adv);
    init_deg_kernel<<<(NN + 255) / 256, 256>>>();
    count_deg_kernel<<<(EE + 255) / 256, 256>>>(ei);
    scan_block_kernel<<<NB_SCAN, 1024>>>();
    scan_sums_kernel<<<1, 32>>>();
    scan_add_kernel<<<NB_SCAN, 1024>>>();
    scatter_kernel<<<(EE + NN + 255) / 256, 256>>>(ei);
    aggregate_kernel<<<(NN + 7) / 8, 256>>>(bias, out);
}

// round 2
// speedup vs baseline: 1.1606x; 1.1606x over previous
#include <cuda_runtime.h>
#include <cstdint>

#define NN 100000
#define EE 1600000
#define HF 128          // HEADS * OUT_F
#define NB_SCAN 98      // ceil(NN/1024)
#define NGEMM 1563      // ceil(NN/64) gemm blocks (64 rows each)
#define NCOUNT 6250     // ceil(EE/256) count blocks

// ---------------- scratch (static __device__, no allocations) ----------------
__device__ float g_h[NN * HF];          // 51.2 MB : h = x @ W
__device__ float g_asrc[NN * 4];
__device__ float g_adst[NN * 4];
__device__ int   g_deg[NN];             // in-degree (self loop added in scan)
__device__ int   g_cursor[NN];
__device__ int   g_rowstart[NN + 1];
__device__ int   g_srcs[EE + NN];
__device__ int   g_bsums[NB_SCAN];
__device__ int   g_is64;

// ---------------- packed fp32x2 FMA helpers ----------------
__device__ __forceinline__ unsigned long long pack2(float lo, float hi) {
    unsigned long long r;
    asm("mov.b64 %0, {%1, %2};" : "=l"(r) : "f"(lo), "f"(hi));
    return r;
}
__device__ __forceinline__ void unpack2(unsigned long long v, float& lo, float& hi) {
    asm("mov.b64 {%0, %1}, %2;" : "=f"(lo), "=f"(hi) : "l"(v));
}
#define FFMA2(acc, a, b) asm("fma.rn.f32x2 %0, %1, %2, %0;" : "+l"(acc) : "l"(a), "l"(b))

// ---------------- kernel 1: dtype detect + zero init ----------------
__global__ void init_kernel(const int* ei32) {
    if (blockIdx.x == 0) {
        __shared__ int nz;
        if (threadIdx.x == 0) nz = 0;
        __syncthreads();
        int v = ei32[threadIdx.x * 2 + 1];  // odd words all-zero => int64
        if (v != 0) atomicAdd(&nz, 1);
        __syncthreads();
        if (threadIdx.x == 0) g_is64 = (nz == 0) ? 1 : 0;
    }
    int i = blockIdx.x * blockDim.x + threadIdx.x;
    if (i < NN) { g_deg[i] = 0; g_cursor[i] = 0; }
}

// ---------------- kernel 2: fused GEMM (+attention epilogue) + degree count ----
// gemm blocks: 64 rows/block, 8 rows/warp, lane owns cols [lane*4, lane*4+4)
// count blocks (bid >= NGEMM): degree histogram for CSR
__global__ __launch_bounds__(256) void gemm_count_kernel(
    const float* __restrict__ x, const float* __restrict__ W,
    const float* __restrict__ att_src, const float* __restrict__ att_dst,
    const void* __restrict__ eiv) {
    if (blockIdx.x >= NGEMM) {
        int t = (blockIdx.x - NGEMM) * 256 + threadIdx.x;
        if (t < EE) {
            int dst;
            if (g_is64) dst = (int)((const long long*)eiv)[EE + t];
            else        dst = ((const int*)eiv)[EE + t];
            atomicAdd(&g_deg[dst], 1);
        }
        return;
    }

    __shared__ float xs[64 * HF];  // 32 KB
    const int warp = threadIdx.x >> 5;
    const int lane = threadIdx.x & 31;
    const int blk_row0 = blockIdx.x * 64;

    // stage 64 rows of x
#pragma unroll
    for (int it = 0; it < 8; it++) {
        int idx = it * 256 + threadIdx.x;      // float4 index
        int row = idx >> 5, c4 = idx & 31;
        float4 v = make_float4(0.f, 0.f, 0.f, 0.f);
        if (blk_row0 + row < NN) v = *(const float4*)(x + (size_t)(blk_row0 + row) * HF + c4 * 4);
        *(float4*)(xs + row * HF + c4 * 4) = v;
    }
    __syncthreads();

    const float* xw = xs + warp * 8 * HF;   // this warp's 8 rows
    unsigned long long acc01[8], acc23[8];
    const unsigned long long z = pack2(0.f, 0.f);
#pragma unroll
    for (int r = 0; r < 8; r++) { acc01[r] = z; acc23[r] = z; }

#pragma unroll 4
    for (int k = 0; k < HF; k += 2) {
        float4 w0 = *(const float4*)(W + k * HF + lane * 4);
        float4 w1 = *(const float4*)(W + (k + 1) * HF + lane * 4);
        unsigned long long w0_01 = pack2(w0.x, w0.y), w0_23 = pack2(w0.z, w0.w);
        unsigned long long w1_01 = pack2(w1.x, w1.y), w1_23 = pack2(w1.z, w1.w);
#pragma unroll
        for (int r = 0; r < 8; r++) {
            float2 xk = *(const float2*)(xw + r * HF + k);
            unsigned long long s0 = pack2(xk.x, xk.x);
            unsigned long long s1 = pack2(xk.y, xk.y);
            FFMA2(acc01[r], s0, w0_01);
            FFMA2(acc23[r], s0, w0_23);
            FFMA2(acc01[r], s1, w1_01);
            FFMA2(acc23[r], s1, w1_23);
        }
    }

    const int head = lane >> 3;
    const int fo   = (lane & 7) * 4;
    float4 s4 = *(const float4*)(att_src + head * 32 + fo);
    float4 d4 = *(const float4*)(att_dst + head * 32 + fo);

#pragma unroll
    for (int r = 0; r < 8; r++) {
        int row = blk_row0 + warp * 8 + r;
        if (row >= NN) continue;
        float4 a;
        unpack2(acc01[r], a.x, a.y);
        unpack2(acc23[r], a.z, a.w);
        *(float4*)(g_h + (size_t)row * HF + lane * 4) = a;
        float ps = a.x * s4.x + a.y * s4.y + a.z * s4.z + a.w * s4.w;
        float pd = a.x * d4.x + a.y * d4.y + a.z * d4.z + a.w * d4.w;
#pragma unroll
        for (int o = 1; o < 8; o <<= 1) {
            ps += __shfl_xor_sync(0xFFFFFFFFu, ps, o);
            pd += __shfl_xor_sync(0xFFFFFFFFu, pd, o);
        }
        if ((lane & 7) == 0) {
            g_asrc[row * 4 + head] = ps;
            g_adst[row * 4 + head] = pd;
        }
    }
}

// ---------------- CSR scan ----------------
__global__ void scan_block_kernel() {
    __shared__ int sm[1024];
    int i = blockIdx.x * 1024 + threadIdx.x;
    int v = (i < NN) ? (g_deg[i] + 1) : 0;  // +1 self loop
    sm[threadIdx.x] = v;
    __syncthreads();
    for (int o = 1; o < 1024; o <<= 1) {
        int t = (threadIdx.x >= (unsigned)o) ? sm[threadIdx.x - o] : 0;
        __syncthreads();
        sm[threadIdx.x] += t;
        __syncthreads();
    }
    if (i < NN) g_rowstart[i] = sm[threadIdx.x] - v;
    if (threadIdx.x == 1023) g_bsums[blockIdx.x] = sm[1023];
}

__global__ void scan_sums_kernel() {  // 1 block of 128: parallel exclusive scan
    __shared__ int sm[128];
    int v = (threadIdx.x < NB_SCAN) ? g_bsums[threadIdx.x] : 0;
    sm[threadIdx.x] = v;
    __syncthreads();
    for (int o = 1; o < 128; o <<= 1) {
        int t = (threadIdx.x >= (unsigned)o) ? sm[threadIdx.x - o] : 0;
        __syncthreads();
        sm[threadIdx.x] += t;
        __syncthreads();
    }
    if (threadIdx.x < NB_SCAN) g_bsums[threadIdx.x] = sm[threadIdx.x] - v;
}

__global__ void scan_add_kernel() {
    int i = blockIdx.x * 1024 + threadIdx.x;
    if (i < NN) g_rowstart[i] += g_bsums[blockIdx.x];
    if (blockIdx.x == 0 && threadIdx.x == 0) g_rowstart[NN] = EE + NN;
}

__global__ void scatter_kernel(const void* eiv) {
    int t = blockIdx.x * blockDim.x + threadIdx.x;
    if (t >= EE + NN) return;
    int s, d;
    if (t < EE) {
        if (g_is64) {
            s = (int)((const long long*)eiv)[t];
            d = (int)((const long long*)eiv)[EE + t];
        } else {
            s = ((const int*)eiv)[t];
            d = ((const int*)eiv)[EE + t];
        }
    } else {
        s = d = t - EE;  // self loop
    }
    int p = atomicAdd(&g_cursor[d], 1);
    g_srcs[g_rowstart[d] + p] = s;
}

// ---------------- per-destination softmax + weighted aggregation ----------------
__global__ __launch_bounds__(256) void aggregate_kernel(
    const float* __restrict__ bias, float* __restrict__ out) {
    const int warp = threadIdx.x >> 5;
    const int lane = threadIdx.x & 31;
    const int i = blockIdx.x * 8 + warp;
    if (i >= NN) return;

    const int head = lane >> 3;
    const float adst = g_adst[i * 4 + head];
    const int start = g_rowstart[i];
    const int end   = g_rowstart[i + 1];

    float4 acc = make_float4(0.f, 0.f, 0.f, 0.f);
    float ssum = 0.f;

    int src_next = g_srcs[start];
    for (int j = start; j < end; j++) {
        int src = src_next;
        if (j + 1 < end) src_next = g_srcs[j + 1];
        float e = g_asrc[src * 4 + head] + adst;
        e = (e > 0.f) ? e : 0.2f * e;
        float w = __expf(e);
        float4 hv = *(const float4*)(g_h + (size_t)src * HF + lane * 4);
        ssum += w;
        acc.x += w * hv.x;
        acc.y += w * hv.y;
        acc.z += w * hv.z;
        acc.w += w * hv.w;
    }

    float inv = 1.f / ssum;
    float4 b = *(const float4*)(bias + lane * 4);
    float4 o;
    o.x = acc.x * inv + b.x;
    o.y = acc.y * inv + b.y;
    o.z = acc.z * inv + b.z;
    o.w = acc.w * inv + b.w;
    *(float4*)(out + (size_t)i * HF + lane * 4) = o;
}

// ---------------- launch ----------------
extern "C" void kernel_launch(void* const* d_in, const int* in_sizes, int n_in,
                              void* d_out, int out_size) {
    const float* x    = (const float*)d_in[0];
    const void*  ei   = d_in[1];
    const float* W    = (const float*)d_in[2];
    const float* asv  = (const float*)d_in[3];
    const float* adv  = (const float*)d_in[4];
    const float* bias = (const float*)d_in[5];
    float* out = (float*)d_out;

    init_kernel<<<(NN + 255) / 256, 256>>>((const int*)ei);
    gemm_count_kernel<<<NGEMM + NCOUNT, 256>>>(x, W, asv, adv, ei);
    scan_block_kernel<<<NB_SCAN, 1024>>>();
    scan_sums_kernel<<<1, 128>>>();
    scan_add_kernel<<<NB_SCAN, 1024>>>();
    scatter_kernel<<<(EE + NN + 255) / 256, 256>>>(ei);
    aggregate_kernel<<<(NN + 7) / 8, 256>>>(bias, out);
}